// round 12
// baseline (speedup 1.0000x reference)
#include <cuda_runtime.h>
#include <cooperative_groups.h>

namespace cg = cooperative_groups;

#define BATCH 64
#define TT    1000
#define SDIM  96
#define ADIM  32
#define HDIM  256
#define INPD  128
#define MROWS (BATCH * TT)   // 64000

typedef unsigned long long u64t;

__device__ __forceinline__ u64t pack2(float lo, float hi) {
    u64t r; asm("mov.b64 %0, {%1, %2};" : "=l"(r) : "f"(lo), "f"(hi)); return r;
}
__device__ __forceinline__ u64t bcast2(float v) { return pack2(v, v); }
__device__ __forceinline__ u64t fma2(u64t a, u64t b, u64t c) {
    u64t d; asm("fma.rn.f32x2 %0, %1, %2, %3;" : "=l"(d) : "l"(a), "l"(b), "l"(c)); return d;
}
__device__ __forceinline__ float2 unpk(u64t v) {
    float2 f; asm("mov.b64 {%0, %1}, %2;" : "=f"(f.x), "=f"(f.y) : "l"(v)); return f;
}

// ---------------- scratch (device globals; no runtime allocation) ----------
__device__ float g_x1[2 * MROWS * HDIM];    // relu(x @ fc_w), per branch
__device__ float g_pre[2 * MROWS * HDIM];   // x1 @ W_ih + (b_hh+b_ih), per branch
__device__ float g_hist[2 * MROWS * HDIM];  // h_t history, per branch

// ======================= GEMM: C[M,256] = op(A @ W + bias) =================
// (unchanged from R8 — passing)
template <int K, bool CONCAT, bool RELU, bool BIAS2>
__global__ __launch_bounds__(256, 2)
void gemm_kernel(const float* __restrict__ A0, const float* __restrict__ A1,
                 const float* __restrict__ Aact,
                 const float* __restrict__ W0, const float* __restrict__ W1,
                 const float* __restrict__ bA0, const float* __restrict__ bB0,
                 const float* __restrict__ bA1, const float* __restrict__ bB1,
                 float* __restrict__ C0, float* __restrict__ C1)
{
    constexpr int ASTR = 68;
    __shared__ float As[2][8][ASTR];
    __shared__ float Bs[2][8][128];

    const int z = blockIdx.z;
    const float* __restrict__ A  = z ? A1 : A0;
    const float* __restrict__ W  = z ? W1 : W0;
    const float* __restrict__ bA = z ? bA1 : bA0;
    const float* __restrict__ bB = z ? bB1 : bB0;
    float* __restrict__ C        = z ? C1 : C0;

    const int tid = threadIdx.x;
    const int mBase = blockIdx.x * 64;
    const int nBase = blockIdx.y * 128;

    const int warp = tid >> 5, lane = tid & 31;
    const int wm = warp & 1, wn = warp >> 1;
    const int lx = lane & 7, ly = lane >> 3;
    const int rowB = wm * 32 + lx * 4;
    const int colB = wn * 32 + ly * 8;

    const int am = tid >> 1, ak = (tid & 1) * 4;
    const int bkr = tid >> 5, bnc = (tid & 31) * 4;

    auto loadA = [&](int kt) -> float4 {
        const int m = mBase + am;
        const int k = kt + ak;
        if (CONCAT) {
            if (k < SDIM) return *(const float4*)(A + (size_t)m * SDIM + k);
            else          return *(const float4*)(Aact + (size_t)m * ADIM + (k - SDIM));
        }
        return *(const float4*)(A + (size_t)m * K + k);
    };

    if (tid < 128) {
        const float4 v = loadA(0);
        As[0][ak + 0][am] = v.x; As[0][ak + 1][am] = v.y;
        As[0][ak + 2][am] = v.z; As[0][ak + 3][am] = v.w;
    }
    *(float4*)&Bs[0][bkr][bnc] = *(const float4*)(W + (size_t)bkr * HDIM + nBase + bnc);
    __syncthreads();

    u64t acc2[4][4];
#pragma unroll
    for (int i = 0; i < 4; i++)
#pragma unroll
        for (int j = 0; j < 4; j++) acc2[i][j] = 0ull;

    int cur = 0;
    for (int kt = 0; kt < K; kt += 8) {
        float4 an, bn;
        const bool more = (kt + 8 < K);
        if (more) {
            if (tid < 128) an = loadA(kt + 8);
            bn = *(const float4*)(W + (size_t)(kt + 8 + bkr) * HDIM + nBase + bnc);
        }
#pragma unroll
        for (int kk = 0; kk < 8; kk++) {
            const float4 a0 = *(const float4*)&As[cur][kk][rowB];
            u64t bp[4];
            asm("ld.shared.v2.u64 {%0, %1}, [%2];"
                : "=l"(bp[0]), "=l"(bp[1])
                : "r"((unsigned)__cvta_generic_to_shared(&Bs[cur][kk][colB])));
            asm("ld.shared.v2.u64 {%0, %1}, [%2];"
                : "=l"(bp[2]), "=l"(bp[3])
                : "r"((unsigned)__cvta_generic_to_shared(&Bs[cur][kk][colB + 4])));
            const float av[4] = {a0.x, a0.y, a0.z, a0.w};
#pragma unroll
            for (int i = 0; i < 4; i++) {
                const u64t ab = bcast2(av[i]);
#pragma unroll
                for (int j = 0; j < 4; j++)
                    acc2[i][j] = fma2(ab, bp[j], acc2[i][j]);
            }
        }
        if (more) {
            if (tid < 128) {
                As[cur ^ 1][ak + 0][am] = an.x; As[cur ^ 1][ak + 1][am] = an.y;
                As[cur ^ 1][ak + 2][am] = an.z; As[cur ^ 1][ak + 3][am] = an.w;
            }
            *(float4*)&Bs[cur ^ 1][bkr][bnc] = bn;
            __syncthreads();
            cur ^= 1;
        }
    }

    float4 bb0 = *(const float4*)&bA[nBase + colB];
    float4 bb1 = *(const float4*)&bA[nBase + colB + 4];
    if (BIAS2) {
        const float4 c0 = *(const float4*)&bB[nBase + colB];
        const float4 c1 = *(const float4*)&bB[nBase + colB + 4];
        bb0.x += c0.x; bb0.y += c0.y; bb0.z += c0.z; bb0.w += c0.w;
        bb1.x += c1.x; bb1.y += c1.y; bb1.z += c1.z; bb1.w += c1.w;
    }
#pragma unroll
    for (int i = 0; i < 4; i++) {
        const size_t gm = mBase + rowB + i;
        const float2 p0 = unpk(acc2[i][0]), p1 = unpk(acc2[i][1]);
        const float2 p2 = unpk(acc2[i][2]), p3 = unpk(acc2[i][3]);
        float4 o0 = {p0.x + bb0.x, p0.y + bb0.y, p1.x + bb0.z, p1.y + bb0.w};
        float4 o1 = {p2.x + bb1.x, p2.y + bb1.y, p3.x + bb1.z, p3.y + bb1.w};
        if (RELU) {
            o0.x = fmaxf(o0.x, 0.f); o0.y = fmaxf(o0.y, 0.f);
            o0.z = fmaxf(o0.z, 0.f); o0.w = fmaxf(o0.w, 0.f);
            o1.x = fmaxf(o1.x, 0.f); o1.y = fmaxf(o1.y, 0.f);
            o1.z = fmaxf(o1.z, 0.f); o1.w = fmaxf(o1.w, 0.f);
        }
        *(float4*)(C + gm * HDIM + nBase + colB)     = o0;
        *(float4*)(C + gm * HDIM + nBase + colB + 4) = o1;
    }
}

// ======================= recurrence (k-split + overlapped exchange) ========
// 64 clusters x 2 CTAs; branch=cid/32, rows {2r,2r+1}. CTA rank owns
// k-range == output cols [rank*128,+128); h stays LOCAL. Per step:
//   pass A: partials for PEER's 128 cols from my h-half  -> reduce -> bulk
//   pass B: partials for MY cols (overlaps the 1024B DSMEM transfer)
//   wait peer partial -> add + pre -> sigmoid -> publish h locally.
// Barrier: same R8-proven expect_tx(1024)/complete_tx recycling, 2 parities.

__device__ __forceinline__ void mbar_wait(uint32_t mbar, uint32_t parity)
{
    uint32_t done;
    asm volatile(
        "{\n\t.reg .pred p;\n\t"
        "mbarrier.try_wait.parity.shared::cta.b64 p, [%1], %2;\n\t"
        "selp.b32 %0, 1, 0, p;\n\t}"
        : "=r"(done) : "r"(mbar), "r"(parity) : "memory");
    if (!done) {
        asm volatile(
            "{\n\t.reg .pred P1;\n\t"
            "WL%=:\n\t"
            "mbarrier.try_wait.parity.shared::cta.b64 P1, [%0], %1, 0x989680;\n\t"
            "@P1 bra.uni WD%=;\n\t"
            "bra.uni WL%=;\n\t"
            "WD%=:\n\t}"
            :: "r"(mbar), "r"(parity) : "memory");
    }
}

__global__ void __cluster_dims__(2, 1, 1) __launch_bounds__(256, 1)
rnn_kernel(const float* __restrict__ pre1, const float* __restrict__ pre2,
           const float* __restrict__ Whh1, const float* __restrict__ Whh2,
           const float* __restrict__ hn, float* __restrict__ hist)
{
    __shared__ alignas(16) u64t  hdup[2 * 128];      // [row][pair] local h half
    __shared__ alignas(16) float psum[8 * 2 * 128];  // [phase][row][col128]
    __shared__ alignas(16) float pout[2 * 128];      // outgoing partial (1024B)
    __shared__ alignas(16) float pin[2][2 * 128];    // [buf][row*128+col] incoming
    __shared__ alignas(16) unsigned long long mbars[2];

    cg::cluster_group cluster = cg::this_cluster();
    const int rank = (int)cluster.block_rank();
    const int cid  = blockIdx.x >> 1;
    const int branch = cid >> 5;
    const int row0 = (cid & 31) * 2;
    const int tid = threadIdx.x;

    const float* __restrict__ pre = branch ? pre2 : pre1;
    const float* __restrict__ Whh = branch ? Whh2 : Whh1;

    const uint32_t mb0 = (uint32_t)__cvta_generic_to_shared(&mbars[0]);
    const uint32_t mb1 = (uint32_t)__cvta_generic_to_shared(&mbars[1]);
    const uint32_t pout_s = (uint32_t)__cvta_generic_to_shared(&pout[0]);
    const uint32_t pin_s  = (uint32_t)__cvta_generic_to_shared(&pin[0][0]);
    uint32_t pmb0, pmb1, ppin;
    asm("mapa.shared::cluster.u32 %0, %1, %2;" : "=r"(pmb0) : "r"(mb0), "r"(rank ^ 1));
    asm("mapa.shared::cluster.u32 %0, %1, %2;" : "=r"(pmb1) : "r"(mb1), "r"(rank ^ 1));
    asm("mapa.shared::cluster.u32 %0, %1, %2;" : "=r"(ppin) : "r"(pin_s), "r"(rank ^ 1));

    // ---- thread roles ----
    const int phase = tid >> 5;          // 8 phases x 16 k within my 128-k half
    const int cg4   = tid & 31;          // 4-col group within a 128-col half
    const int K0    = rank * 128;        // my k-range and my output col base
    const int ksub  = phase * 16;

    // ---- W slices into registers: pass A (peer cols), pass B (my cols) ----
    u64t wA[16][2], wB[16][2];
    {
        const float* wgA = Whh + (size_t)(K0 + ksub) * HDIM + (rank ^ 1) * 128 + (cg4 << 2);
        const float* wgB = Whh + (size_t)(K0 + ksub) * HDIM + rank * 128 + (cg4 << 2);
#pragma unroll
        for (int kk = 0; kk < 16; kk++) {
            const float4 va = *(const float4*)(wgA + kk * HDIM);
            const float4 vb = *(const float4*)(wgB + kk * HDIM);
            wA[kk][0] = pack2(va.x, va.y); wA[kk][1] = pack2(va.z, va.w);
            wB[kk][0] = pack2(vb.x, vb.y); wB[kk][1] = pack2(vb.z, vb.w);
        }
    }
    // h0 (my k-half, both rows, duplicated pairs): one entry per thread
    {
        const int r = tid >> 7, idx = tid & 127;
        const float v = hn[(row0 + r) * HDIM + K0 + idx];
        hdup[r * 128 + idx] = pack2(v, v);
    }
    if (tid == 0) {
        asm volatile("mbarrier.init.shared.b64 [%0], %1;" :: "r"(mb0), "r"(1u) : "memory");
        asm volatile("mbarrier.init.shared.b64 [%0], %1;" :: "r"(mb1), "r"(1u) : "memory");
        asm volatile("mbarrier.arrive.expect_tx.shared.b64 _, [%0], %1;"
                     :: "r"(mb0), "r"(1024u) : "memory");
        asm volatile("mbarrier.arrive.expect_tx.shared.b64 _, [%0], %1;"
                     :: "r"(mb1), "r"(1024u) : "memory");
    }
    __syncthreads();
    cluster.sync();

    const int myrow = tid >> 7;
    const int rcol  = tid & 127;
    const int gcol  = K0 + rcol;         // my output col
    const float* pre_base = pre + ((size_t)(row0 + myrow) * TT) * HDIM + gcol;
    float* hist_base = hist + ((size_t)(branch * BATCH + row0 + myrow) * TT) * HDIM + gcol;
    float pf = pre_base[0];

    for (int t = 0; t < TT; t++) {
        const int q = t & 1;
        const uint32_t par = (uint32_t)((t >> 1) & 1);
        const uint32_t mbq  = q ? mb1 : mb0;
        const uint32_t pmbq = q ? pmb1 : pmb0;

        // ---- load my h-sub once (both rows), reuse in both passes ----
        const u64t* h0p = &hdup[ksub];
        const u64t* h1p = &hdup[128 + ksub];

        // ================= pass A: peer's cols =================
        {
            u64t a00 = 0ull, a01 = 0ull, a10 = 0ull, a11 = 0ull;
#pragma unroll
            for (int kk = 0; kk < 16; kk += 2) {
                const ulonglong2 hb0 = *(const ulonglong2*)(h0p + kk);
                const ulonglong2 hb1 = *(const ulonglong2*)(h1p + kk);
                a00 = fma2(hb0.x, wA[kk][0], a00);     a01 = fma2(hb0.x, wA[kk][1], a01);
                a10 = fma2(hb1.x, wA[kk][0], a10);     a11 = fma2(hb1.x, wA[kk][1], a11);
                a00 = fma2(hb0.y, wA[kk + 1][0], a00); a01 = fma2(hb0.y, wA[kk + 1][1], a01);
                a10 = fma2(hb1.y, wA[kk + 1][0], a10); a11 = fma2(hb1.y, wA[kk + 1][1], a11);
            }
            *(ulonglong2*)&psum[(phase * 2 + 0) * 128 + (cg4 << 2)] = make_ulonglong2(a00, a01);
            *(ulonglong2*)&psum[(phase * 2 + 1) * 128 + (cg4 << 2)] = make_ulonglong2(a10, a11);
        }
        __syncthreads();
        {   // reduce A -> pout
            float s = 0.f;
#pragma unroll
            for (int p = 0; p < 8; p++) s += psum[(p * 2 + myrow) * 128 + rcol];
            pout[myrow * 128 + rcol] = s;
        }
        __syncthreads();
        // ---- send my partial for peer's cols (1024B) ----
        if (tid == 0) {
            asm volatile("fence.proxy.async.shared::cta;" ::: "memory");
            asm volatile(
                "cp.async.bulk.shared::cluster.shared::cta.mbarrier::complete_tx::bytes "
                "[%0], [%1], %2, [%3];"
                :: "r"(ppin + (uint32_t)(q * 1024)), "r"(pout_s), "r"(1024u), "r"(pmbq)
                : "memory");
        }

        // ================= pass B: my cols (overlaps transfer) =================
        {
            u64t a00 = 0ull, a01 = 0ull, a10 = 0ull, a11 = 0ull;
#pragma unroll
            for (int kk = 0; kk < 16; kk += 2) {
                const ulonglong2 hb0 = *(const ulonglong2*)(h0p + kk);
                const ulonglong2 hb1 = *(const ulonglong2*)(h1p + kk);
                a00 = fma2(hb0.x, wB[kk][0], a00);     a01 = fma2(hb0.x, wB[kk][1], a01);
                a10 = fma2(hb1.x, wB[kk][0], a10);     a11 = fma2(hb1.x, wB[kk][1], a11);
                a00 = fma2(hb0.y, wB[kk + 1][0], a00); a01 = fma2(hb0.y, wB[kk + 1][1], a01);
                a10 = fma2(hb1.y, wB[kk + 1][0], a10); a11 = fma2(hb1.y, wB[kk + 1][1], a11);
            }
            *(ulonglong2*)&psum[(phase * 2 + 0) * 128 + (cg4 << 2)] = make_ulonglong2(a00, a01);
            *(ulonglong2*)&psum[(phase * 2 + 1) * 128 + (cg4 << 2)] = make_ulonglong2(a10, a11);
        }
        __syncthreads();

        // ---- reduce B, wait peer partial, finalize ----
        {
            float s = 0.f;
#pragma unroll
            for (int p = 0; p < 8; p++) s += psum[(p * 2 + myrow) * 128 + rcol];
            mbar_wait(mbq, par);
            const float v = s + pin[q][myrow * 128 + rcol] + pf;
            const float hv = 1.f / (1.f + __expf(-v));
            hdup[myrow * 128 + rcol] = pack2(hv, hv);   // local publish only
            hist_base[(size_t)t * HDIM] = hv;           // fire-and-forget
            if (t + 1 < TT) pf = pre_base[(size_t)(t + 1) * HDIM];
        }
        if (tid == 0)   // recycle expect for this barrier's next phase (t+2)
            asm volatile("mbarrier.arrive.expect_tx.shared.b64 _, [%0], %1;"
                         :: "r"(mbq), "r"(1024u) : "memory");
        __syncthreads();   // h_t + pin consumption complete before next step
    }
    cluster.sync();   // no CTA exits with peer-bound bulks in flight
}

// ======================= q projection (memory-bound GEMV) ==================
__global__ __launch_bounds__(256)
void q_kernel(const float* __restrict__ hist,
              const float* __restrict__ qw1, const float* __restrict__ qb1,
              const float* __restrict__ qw2, const float* __restrict__ qb2,
              float* __restrict__ out)
{
    __shared__ float qs[2][256];
    const int tid = threadIdx.x;
    qs[0][tid] = qw1[tid];
    qs[1][tid] = qw2[tid];
    __syncthreads();

    const int warp = tid >> 5, lane = tid & 31;
    const size_t gid = (size_t)blockIdx.x * 8 + warp;   // (branch,row,t)
    const int branch = (gid >= (size_t)MROWS) ? 1 : 0;
    const float* h = hist + gid * HDIM;
    float s = 0.f;
#pragma unroll
    for (int m = 0; m < 256; m += 32)
        s = fmaf(h[m + lane], qs[branch][m + lane], s);
#pragma unroll
    for (int o = 16; o; o >>= 1)
        s += __shfl_xor_sync(0xffffffffu, s, o);
    if (lane == 0)
        out[gid] = s + (branch ? qb2[0] : qb1[0]);
}

// ---------------------------------------------------------------------------
extern "C" void kernel_launch(void* const* d_in, const int* in_sizes, int n_in,
                              void* d_out, int out_size)
{
    (void)in_sizes; (void)n_in; (void)out_size;
    const float* state  = (const float*)d_in[0];
    const float* action = (const float*)d_in[1];
    const float* hn     = (const float*)d_in[2];
    const float* fc11_w = (const float*)d_in[3];
    const float* fc11_b = (const float*)d_in[4];
    const float* W_hh1  = (const float*)d_in[5];
    const float* W_ih1  = (const float*)d_in[6];
    const float* b_hh1  = (const float*)d_in[7];
    const float* b_ih1  = (const float*)d_in[8];
    const float* fc12_w = (const float*)d_in[9];
    const float* fc12_b = (const float*)d_in[10];
    const float* fc21_w = (const float*)d_in[11];
    const float* fc21_b = (const float*)d_in[12];
    const float* W_hh2  = (const float*)d_in[13];
    const float* W_ih2  = (const float*)d_in[14];
    const float* b_hh2  = (const float*)d_in[15];
    const float* b_ih2  = (const float*)d_in[16];
    const float* fc22_w = (const float*)d_in[17];
    const float* fc22_b = (const float*)d_in[18];
    float* out = (float*)d_out;

    float *x1p, *prep, *histp;
    cudaGetSymbolAddress((void**)&x1p,  g_x1);
    cudaGetSymbolAddress((void**)&prep, g_pre);
    cudaGetSymbolAddress((void**)&histp, g_hist);
    float* x1a  = x1p;
    float* x1b  = x1p + (size_t)MROWS * HDIM;
    float* pre1 = prep;
    float* pre2 = prep + (size_t)MROWS * HDIM;

    const dim3 grid(MROWS / 64, HDIM / 128, 2);
    const dim3 blk(256);

    gemm_kernel<INPD, true, true, false><<<grid, blk>>>(
        state, state, action, fc11_w, fc21_w,
        fc11_b, nullptr, fc21_b, nullptr, x1a, x1b);
    gemm_kernel<HDIM, false, false, true><<<grid, blk>>>(
        x1a, x1b, nullptr, W_ih1, W_ih2,
        b_hh1, b_ih1, b_hh2, b_ih2, pre1, pre2);
    rnn_kernel<<<128, blk>>>(pre1, pre2, W_hh1, W_hh2, hn, histp);
    q_kernel<<<(2 * MROWS) / 8, blk>>>(histp, fc12_w, fc12_b, fc22_w, fc22_b, out);
}

// round 13
// speedup vs baseline: 1.1742x; 1.1742x over previous
#include <cuda_runtime.h>
#include <cooperative_groups.h>

namespace cg = cooperative_groups;

#define BATCH 64
#define TT    1000
#define SDIM  96
#define ADIM  32
#define HDIM  256
#define INPD  128
#define MROWS (BATCH * TT)   // 64000

typedef unsigned long long u64t;

__device__ __forceinline__ u64t pack2(float lo, float hi) {
    u64t r; asm("mov.b64 %0, {%1, %2};" : "=l"(r) : "f"(lo), "f"(hi)); return r;
}
__device__ __forceinline__ u64t bcast2(float v) { return pack2(v, v); }
__device__ __forceinline__ u64t fma2(u64t a, u64t b, u64t c) {
    u64t d; asm("fma.rn.f32x2 %0, %1, %2, %3;" : "=l"(d) : "l"(a), "l"(b), "l"(c)); return d;
}
__device__ __forceinline__ float2 unpk(u64t v) {
    float2 f; asm("mov.b64 {%0, %1}, %2;" : "=f"(f.x), "=f"(f.y) : "l"(v)); return f;
}

// ---------------- scratch (device globals; no runtime allocation) ----------
__device__ float g_x1[2 * MROWS * HDIM];    // relu(x @ fc_w), per branch
__device__ float g_pre[2 * MROWS * HDIM];   // x1 @ W_ih + (b_hh+b_ih), per branch
__device__ float g_hist[2 * MROWS * HDIM];  // h_t history, per branch

// ======================= GEMM: C[M,256] = op(A @ W + bias) =================
// (unchanged from R8 — passing)
template <int K, bool CONCAT, bool RELU, bool BIAS2>
__global__ __launch_bounds__(256, 2)
void gemm_kernel(const float* __restrict__ A0, const float* __restrict__ A1,
                 const float* __restrict__ Aact,
                 const float* __restrict__ W0, const float* __restrict__ W1,
                 const float* __restrict__ bA0, const float* __restrict__ bB0,
                 const float* __restrict__ bA1, const float* __restrict__ bB1,
                 float* __restrict__ C0, float* __restrict__ C1)
{
    constexpr int ASTR = 68;
    __shared__ float As[2][8][ASTR];
    __shared__ float Bs[2][8][128];

    const int z = blockIdx.z;
    const float* __restrict__ A  = z ? A1 : A0;
    const float* __restrict__ W  = z ? W1 : W0;
    const float* __restrict__ bA = z ? bA1 : bA0;
    const float* __restrict__ bB = z ? bB1 : bB0;
    float* __restrict__ C        = z ? C1 : C0;

    const int tid = threadIdx.x;
    const int mBase = blockIdx.x * 64;
    const int nBase = blockIdx.y * 128;

    const int warp = tid >> 5, lane = tid & 31;
    const int wm = warp & 1, wn = warp >> 1;
    const int lx = lane & 7, ly = lane >> 3;
    const int rowB = wm * 32 + lx * 4;
    const int colB = wn * 32 + ly * 8;

    const int am = tid >> 1, ak = (tid & 1) * 4;
    const int bkr = tid >> 5, bnc = (tid & 31) * 4;

    auto loadA = [&](int kt) -> float4 {
        const int m = mBase + am;
        const int k = kt + ak;
        if (CONCAT) {
            if (k < SDIM) return *(const float4*)(A + (size_t)m * SDIM + k);
            else          return *(const float4*)(Aact + (size_t)m * ADIM + (k - SDIM));
        }
        return *(const float4*)(A + (size_t)m * K + k);
    };

    if (tid < 128) {
        const float4 v = loadA(0);
        As[0][ak + 0][am] = v.x; As[0][ak + 1][am] = v.y;
        As[0][ak + 2][am] = v.z; As[0][ak + 3][am] = v.w;
    }
    *(float4*)&Bs[0][bkr][bnc] = *(const float4*)(W + (size_t)bkr * HDIM + nBase + bnc);
    __syncthreads();

    u64t acc2[4][4];
#pragma unroll
    for (int i = 0; i < 4; i++)
#pragma unroll
        for (int j = 0; j < 4; j++) acc2[i][j] = 0ull;

    int cur = 0;
    for (int kt = 0; kt < K; kt += 8) {
        float4 an, bn;
        const bool more = (kt + 8 < K);
        if (more) {
            if (tid < 128) an = loadA(kt + 8);
            bn = *(const float4*)(W + (size_t)(kt + 8 + bkr) * HDIM + nBase + bnc);
        }
#pragma unroll
        for (int kk = 0; kk < 8; kk++) {
            const float4 a0 = *(const float4*)&As[cur][kk][rowB];
            u64t bp[4];
            asm("ld.shared.v2.u64 {%0, %1}, [%2];"
                : "=l"(bp[0]), "=l"(bp[1])
                : "r"((unsigned)__cvta_generic_to_shared(&Bs[cur][kk][colB])));
            asm("ld.shared.v2.u64 {%0, %1}, [%2];"
                : "=l"(bp[2]), "=l"(bp[3])
                : "r"((unsigned)__cvta_generic_to_shared(&Bs[cur][kk][colB + 4])));
            const float av[4] = {a0.x, a0.y, a0.z, a0.w};
#pragma unroll
            for (int i = 0; i < 4; i++) {
                const u64t ab = bcast2(av[i]);
#pragma unroll
                for (int j = 0; j < 4; j++)
                    acc2[i][j] = fma2(ab, bp[j], acc2[i][j]);
            }
        }
        if (more) {
            if (tid < 128) {
                As[cur ^ 1][ak + 0][am] = an.x; As[cur ^ 1][ak + 1][am] = an.y;
                As[cur ^ 1][ak + 2][am] = an.z; As[cur ^ 1][ak + 3][am] = an.w;
            }
            *(float4*)&Bs[cur ^ 1][bkr][bnc] = bn;
            __syncthreads();
            cur ^= 1;
        }
    }

    float4 bb0 = *(const float4*)&bA[nBase + colB];
    float4 bb1 = *(const float4*)&bA[nBase + colB + 4];
    if (BIAS2) {
        const float4 c0 = *(const float4*)&bB[nBase + colB];
        const float4 c1 = *(const float4*)&bB[nBase + colB + 4];
        bb0.x += c0.x; bb0.y += c0.y; bb0.z += c0.z; bb0.w += c0.w;
        bb1.x += c1.x; bb1.y += c1.y; bb1.z += c1.z; bb1.w += c1.w;
    }
#pragma unroll
    for (int i = 0; i < 4; i++) {
        const size_t gm = mBase + rowB + i;
        const float2 p0 = unpk(acc2[i][0]), p1 = unpk(acc2[i][1]);
        const float2 p2 = unpk(acc2[i][2]), p3 = unpk(acc2[i][3]);
        float4 o0 = {p0.x + bb0.x, p0.y + bb0.y, p1.x + bb0.z, p1.y + bb0.w};
        float4 o1 = {p2.x + bb1.x, p2.y + bb1.y, p3.x + bb1.z, p3.y + bb1.w};
        if (RELU) {
            o0.x = fmaxf(o0.x, 0.f); o0.y = fmaxf(o0.y, 0.f);
            o0.z = fmaxf(o0.z, 0.f); o0.w = fmaxf(o0.w, 0.f);
            o1.x = fmaxf(o1.x, 0.f); o1.y = fmaxf(o1.y, 0.f);
            o1.z = fmaxf(o1.z, 0.f); o1.w = fmaxf(o1.w, 0.f);
        }
        *(float4*)(C + gm * HDIM + nBase + colB)     = o0;
        *(float4*)(C + gm * HDIM + nBase + colB + 4) = o1;
    }
}

// ======================= recurrence (R8 algo, 512 threads) =================
// 64 clusters x 2 CTAs; branch=cid/32, rows {2r,2r+1}; rank owns cols
// [rank*128,+128); W slice in regs as f32x2 pairs, 16 k-phases x 16 k.
// 512 threads = 4 warps/SMSP so LDS/scoreboard stalls are covered by
// warp interleave. Same bulk-DSMEM expect_tx/complete_tx handshake as R8.

__device__ __forceinline__ void mbar_wait(uint32_t mbar, uint32_t parity)
{
    uint32_t done;
    asm volatile(
        "{\n\t.reg .pred p;\n\t"
        "mbarrier.try_wait.parity.shared::cta.b64 p, [%1], %2;\n\t"
        "selp.b32 %0, 1, 0, p;\n\t}"
        : "=r"(done) : "r"(mbar), "r"(parity) : "memory");
    if (!done) {
        asm volatile(
            "{\n\t.reg .pred P1;\n\t"
            "WL%=:\n\t"
            "mbarrier.try_wait.parity.shared::cta.b64 P1, [%0], %1, 0x989680;\n\t"
            "@P1 bra.uni WD%=;\n\t"
            "bra.uni WL%=;\n\t"
            "WD%=:\n\t}"
            :: "r"(mbar), "r"(parity) : "memory");
    }
}

__global__ void __cluster_dims__(2, 1, 1) __launch_bounds__(512, 1)
rnn_kernel(const float* __restrict__ pre1, const float* __restrict__ pre2,
           const float* __restrict__ Whh1, const float* __restrict__ Whh2,
           const float* __restrict__ hn, float* __restrict__ hist)
{
    __shared__ alignas(16) u64t stage[2][2][2][128];  // [buf][src][row][pair]
    __shared__ alignas(16) float psum[16 * 2 * 128];  // [phase][row][128]
    __shared__ alignas(16) unsigned long long mbars[2];

    cg::cluster_group cluster = cg::this_cluster();
    const int rank = (int)cluster.block_rank();
    const int cid  = blockIdx.x >> 1;
    const int branch = cid >> 5;
    const int row0 = (cid & 31) * 2;
    const int tid = threadIdx.x;

    const float* __restrict__ pre = branch ? pre2 : pre1;
    const float* __restrict__ Whh = branch ? Whh2 : Whh1;

    const uint32_t mb0 = (uint32_t)__cvta_generic_to_shared(&mbars[0]);
    const uint32_t mb1 = (uint32_t)__cvta_generic_to_shared(&mbars[1]);
    const uint32_t stg = (uint32_t)__cvta_generic_to_shared(&stage[0][0][0][0]);
    uint32_t pmb0, pmb1, pstg;
    asm("mapa.shared::cluster.u32 %0, %1, %2;" : "=r"(pmb0) : "r"(mb0), "r"(rank ^ 1));
    asm("mapa.shared::cluster.u32 %0, %1, %2;" : "=r"(pmb1) : "r"(mb1), "r"(rank ^ 1));
    asm("mapa.shared::cluster.u32 %0, %1, %2;" : "=r"(pstg) : "r"(stg), "r"(rank ^ 1));

    // ---- W slice into regs: 16 k x 2 col-pairs = 32 u64 (64 regs) ----
    const int colg  = tid & 31;     // 4-col group
    const int phase = tid >> 5;     // k block of 16 (0..15)
    const int k0 = phase * 16;
    u64t w2[16][2];
    {
        const float* wg = Whh + (size_t)k0 * HDIM + rank * 128 + (colg << 2);
#pragma unroll
        for (int j = 0; j < 16; j++) {
            const float4 v = *(const float4*)(wg + j * HDIM);
            w2[j][0] = pack2(v.x, v.y);
            w2[j][1] = pack2(v.z, v.w);
        }
    }
    // h0 -> buf 0, BOTH src halves, both rows (one entry per thread)
    {
        const int src = tid >> 8, r = (tid >> 7) & 1, idx = tid & 127;
        const float v = hn[(row0 + r) * HDIM + src * 128 + idx];
        stage[0][src][r][idx] = pack2(v, v);
    }
    if (tid == 0) {
        asm volatile("mbarrier.init.shared.b64 [%0], %1;" :: "r"(mb0), "r"(1u) : "memory");
        asm volatile("mbarrier.init.shared.b64 [%0], %1;" :: "r"(mb1), "r"(1u) : "memory");
        asm volatile("mbarrier.arrive.expect_tx.shared.b64 _, [%0], %1;"
                     :: "r"(mb0), "r"(2048u) : "memory");
        asm volatile("mbarrier.arrive.expect_tx.shared.b64 _, [%0], %1;"
                     :: "r"(mb1), "r"(2048u) : "memory");
    }
    __syncthreads();
    cluster.sync();     // barriers + expects visible before any peer bulk

    const bool red   = tid < 256;        // reducer threads
    const int  myrow = (tid >> 7) & 1;
    const int  rcol  = tid & 127;
    const int  gcol  = rank * 128 + rcol;
    const float* pre_base = pre + ((size_t)(row0 + myrow) * TT) * HDIM + gcol;
    float* hist_base = hist + ((size_t)(branch * BATCH + row0 + myrow) * TT) * HDIM + gcol;
    float pf = red ? pre_base[0] : 0.f;

    const int src  = k0 >> 7;          // which 128-col half my k-range reads
    const int idx0 = k0 & 127;

    for (int t = 0; t < TT; t++) {
        const int rb = t & 1, wb = (t + 1) & 1;

        if (t) {
            const uint32_t q = (uint32_t)rb;
            mbar_wait(q ? mb1 : mb0, (uint32_t)((t - 1) >> 1) & 1u);
            if (tid == 0)   // expect for this barrier's NEXT phase (step t+2)
                asm volatile("mbarrier.arrive.expect_tx.shared.b64 _, [%0], %1;"
                             :: "r"(q ? mb1 : mb0), "r"(2048u) : "memory");
        }

        // ---- FMA: 2 rows x 2 col-pairs, k in [k0,k0+16) ----
        {
            u64t a00 = 0ull, a01 = 0ull, a10 = 0ull, a11 = 0ull;
            const u64t* h0p = &stage[rb][src][0][idx0];
            const u64t* h1p = &stage[rb][src][1][idx0];
#pragma unroll
            for (int j = 0; j < 16; j += 2) {
                const ulonglong2 hb0 = *(const ulonglong2*)(h0p + j);
                const ulonglong2 hb1 = *(const ulonglong2*)(h1p + j);
                a00 = fma2(hb0.x, w2[j][0], a00);     a01 = fma2(hb0.x, w2[j][1], a01);
                a10 = fma2(hb1.x, w2[j][0], a10);     a11 = fma2(hb1.x, w2[j][1], a11);
                a00 = fma2(hb0.y, w2[j + 1][0], a00); a01 = fma2(hb0.y, w2[j + 1][1], a01);
                a10 = fma2(hb1.y, w2[j + 1][0], a10); a11 = fma2(hb1.y, w2[j + 1][1], a11);
            }
            *(ulonglong2*)&psum[(phase * 2 + 0) * 128 + (colg << 2)] = make_ulonglong2(a00, a01);
            *(ulonglong2*)&psum[(phase * 2 + 1) * 128 + (colg << 2)] = make_ulonglong2(a10, a11);
        }
        __syncthreads();

        // ---- reduce 16 phases, sigmoid, publish local half ----
        if (red) {
            float v = pf;
#pragma unroll
            for (int p = 0; p < 16; p++) v += psum[(p * 2 + myrow) * 128 + rcol];
            const float hv = 1.f / (1.f + __expf(-v));
            stage[wb][rank][myrow][rcol] = pack2(hv, hv);
            hist_base[(size_t)t * HDIM] = hv;                 // fire-and-forget
            if (t + 1 < TT) pf = pre_base[(size_t)(t + 1) * HDIM];
        }
        __syncthreads();   // local half published; psum WAR covered

        // ---- ONE bulk copy of my 2048B half to the peer + tx completion ----
        if (tid == 0 && t + 1 < TT) {
            asm volatile("fence.proxy.async.shared::cta;" ::: "memory");
            const uint32_t off = (uint32_t)(wb * 4096 + rank * 2048);
            asm volatile(
                "cp.async.bulk.shared::cluster.shared::cta.mbarrier::complete_tx::bytes "
                "[%0], [%1], %2, [%3];"
                :: "r"(pstg + off), "r"(stg + off), "r"(2048u),
                   "r"(wb ? pmb1 : pmb0)
                : "memory");
        }
    }
    cluster.sync();   // no CTA exits with peer-bound bulks in flight
}

// ======================= q projection (memory-bound GEMV) ==================
__global__ __launch_bounds__(256)
void q_kernel(const float* __restrict__ hist,
              const float* __restrict__ qw1, const float* __restrict__ qb1,
              const float* __restrict__ qw2, const float* __restrict__ qb2,
              float* __restrict__ out)
{
    __shared__ float qs[2][256];
    const int tid = threadIdx.x;
    qs[0][tid] = qw1[tid];
    qs[1][tid] = qw2[tid];
    __syncthreads();

    const int warp = tid >> 5, lane = tid & 31;
    const size_t gid = (size_t)blockIdx.x * 8 + warp;   // (branch,row,t)
    const int branch = (gid >= (size_t)MROWS) ? 1 : 0;
    const float* h = hist + gid * HDIM;
    float s = 0.f;
#pragma unroll
    for (int m = 0; m < 256; m += 32)
        s = fmaf(h[m + lane], qs[branch][m + lane], s);
#pragma unroll
    for (int o = 16; o; o >>= 1)
        s += __shfl_xor_sync(0xffffffffu, s, o);
    if (lane == 0)
        out[gid] = s + (branch ? qb2[0] : qb1[0]);
}

// ---------------------------------------------------------------------------
extern "C" void kernel_launch(void* const* d_in, const int* in_sizes, int n_in,
                              void* d_out, int out_size)
{
    (void)in_sizes; (void)n_in; (void)out_size;
    const float* state  = (const float*)d_in[0];
    const float* action = (const float*)d_in[1];
    const float* hn     = (const float*)d_in[2];
    const float* fc11_w = (const float*)d_in[3];
    const float* fc11_b = (const float*)d_in[4];
    const float* W_hh1  = (const float*)d_in[5];
    const float* W_ih1  = (const float*)d_in[6];
    const float* b_hh1  = (const float*)d_in[7];
    const float* b_ih1  = (const float*)d_in[8];
    const float* fc12_w = (const float*)d_in[9];
    const float* fc12_b = (const float*)d_in[10];
    const float* fc21_w = (const float*)d_in[11];
    const float* fc21_b = (const float*)d_in[12];
    const float* W_hh2  = (const float*)d_in[13];
    const float* W_ih2  = (const float*)d_in[14];
    const float* b_hh2  = (const float*)d_in[15];
    const float* b_ih2  = (const float*)d_in[16];
    const float* fc22_w = (const float*)d_in[17];
    const float* fc22_b = (const float*)d_in[18];
    float* out = (float*)d_out;

    float *x1p, *prep, *histp;
    cudaGetSymbolAddress((void**)&x1p,  g_x1);
    cudaGetSymbolAddress((void**)&prep, g_pre);
    cudaGetSymbolAddress((void**)&histp, g_hist);
    float* x1a  = x1p;
    float* x1b  = x1p + (size_t)MROWS * HDIM;
    float* pre1 = prep;
    float* pre2 = prep + (size_t)MROWS * HDIM;

    const dim3 grid(MROWS / 64, HDIM / 128, 2);
    const dim3 blk(256);

    gemm_kernel<INPD, true, true, false><<<grid, blk>>>(
        state, state, action, fc11_w, fc21_w,
        fc11_b, nullptr, fc21_b, nullptr, x1a, x1b);
    gemm_kernel<HDIM, false, false, true><<<grid, blk>>>(
        x1a, x1b, nullptr, W_ih1, W_ih2,
        b_hh1, b_ih1, b_hh2, b_ih2, pre1, pre2);
    rnn_kernel<<<128, 512>>>(pre1, pre2, W_hh1, W_hh2, hn, histp);
    q_kernel<<<(2 * MROWS) / 8, blk>>>(histp, fc12_w, fc12_b, fc22_w, fc22_b, out);
}